// round 13
// baseline (speedup 1.0000x reference)
#include <cuda_runtime.h>

// ---------------- constants ----------------
#define FM     48
#define NPATH  11
#define NMAX   1024
#define BB     8
#define PP     2
#define DD     192
#define ZB     592   // zero-fill blocks (4/SM x 148)

// ---------------- device scratch ----------------
__device__ float  g_CG[NPATH * 125];
__device__ float  g_Weff0[144 * 96];          // [u][i]   (lanes i contiguous)
__device__ float  g_Weff1[192 * 48];          // [u][f]
__device__ float  g_Weff2[192 * 48];
__device__ float  g_tpwT[NPATH * 2304];       // [p][v][u] (lanes u contiguous)
__device__ int    g_slotOf[NMAX];             // node -> b*MN+pos (or -1)

// path tables
__constant__ int c_l1[NPATH]   = {0,0,0,1,1,1,1,2,2,2,2};
__constant__ int c_l2[NPATH]   = {0,1,2,0,1,1,2,0,1,2,2};
__constant__ int c_l3[NPATH]   = {0,1,2,1,0,2,1,2,1,0,2};
__constant__ int c_aoff[NPATH] = {0,1,4,9,10,13,16,21,22,25,30};

// a-stage tables: 35 (path,k) slots
__constant__ int c_j_p[35]  = {0, 1,1,1, 2,2,2,2,2, 3, 4,4,4, 5,5,5, 6,6,6,6,6, 7, 8,8,8, 9,9,9,9,9, 10,10,10,10,10};
__constant__ int c_j_c2[35] = {0, 1,2,3, 4,5,6,7,8, 0, 1,2,3, 1,2,3, 4,5,6,7,8, 0, 1,2,3, 4,5,6,7,8, 4,5,6,7,8};

// o-stage tables: 35 (path,c3) outputs; dst = offset in packed o[1680]
__constant__ int c_os_p[35]  = {0, 1,1,1, 2,2,2,2,2, 3,3,3, 4, 5,5,5,5,5, 6,6,6, 7,7,7,7,7, 8,8,8, 9, 10,10,10,10,10};
__constant__ int c_os_c3[35] = {0, 0,1,2, 0,1,2,3,4, 0,1,2, 0, 0,1,2,3,4, 0,1,2, 0,1,2,3,4, 0,1,2, 0, 0,1,2,3,4};
__constant__ int c_os_dst[35]= {0, 144,336,528, 720,912,1104,1296,1488, 192,384,576, 48,
                                768,960,1152,1344,1536, 240,432,624, 816,1008,1200,1392,1584,
                                288,480,672, 96, 864,1056,1248,1440,1632};

// ---------------- CG helpers (fp32, factorials <= 5040 exact) ----------------
struct cplxf { float re, im; };
__device__ __forceinline__ cplxf cmulf(cplxf a, cplxf b){ return {a.re*b.re - a.im*b.im, a.re*b.im + a.im*b.re}; }
__device__ __forceinline__ cplxf cconjf(cplxf a){ return {a.re, -a.im}; }
__device__ float f_fact(int x){ float r = 1.f; for (int i = 2; i <= x; i++) r *= (float)i; return r; }

__device__ float su2_cgf(int j1,int j2,int j3,int m1,int m2,int m3){
    if (m1 + m2 != m3) return 0.f;
    float pre = sqrtf((float)(2*j3+1) * f_fact(j3+j1-j2) * f_fact(j3-j1+j2) * f_fact(j1+j2-j3)
                      / f_fact(j1+j2+j3+1));
    pre *= sqrtf(f_fact(j3+m3)*f_fact(j3-m3)*f_fact(j1-m1)*f_fact(j1+m1)*f_fact(j2-m2)*f_fact(j2+m2));
    float s = 0.f;
    for (int v = 0; v <= j1 + j2 - j3; v++){
        int a1 = j1+j2-j3-v, a2 = j1-m1-v, a3 = j2+m2-v, a4 = j3-j2+m1+v, a5 = j3-j1-m2+v;
        if (a1 < 0 || a2 < 0 || a3 < 0 || a4 < 0 || a5 < 0) continue;
        float den = f_fact(v)*f_fact(a1)*f_fact(a2)*f_fact(a3)*f_fact(a4)*f_fact(a5);
        s += ((v & 1) ? -1.f : 1.f) / den;
    }
    return pre * s;
}

__device__ void u_fillf(int l, cplxf* U){
    int n = 2*l + 1;
    for (int i = 0; i < n*n; i++) U[i] = {0.f, 0.f};
    float s2 = sqrtf(0.5f);
    for (int m = -l; m <= l; m++){
        int a = l + m;
        if (m > 0){
            U[a*n + (l+m)] = {((m & 1) ? -1.f : 1.f) * s2, 0.f};
            U[a*n + (l-m)] = {s2, 0.f};
        } else if (m == 0){
            U[a*n + l] = {1.f, 0.f};
        } else {
            int mm = -m;
            U[a*n + (l+m)] = {0.f, s2};
            U[a*n + (l-m)] = {0.f, -(((mm & 1) ? -1.f : 1.f)) * s2};
        }
    }
}

// ---------------- prep: blocks 0..10 CG | 11 setup | 12.. weff+transpose ----------------
__global__ void __launch_bounds__(256) k_prep(const float* __restrict__ Wo0, const float* __restrict__ Wo1,
                                              const float* __restrict__ Wo2, const float* __restrict__ Wt0,
                                              const float* __restrict__ Wt1, const float* __restrict__ Wt2,
                                              const float* __restrict__ tpw, const int* __restrict__ batch,
                                              int n, int MN){
    int bid = blockIdx.x, tid = threadIdx.x;

    if (bid < NPATH){
        int p = bid;
        int l1 = c_l1[p], l2 = c_l2[p], l3 = c_l3[p];
        int n1 = 2*l1+1, n2 = 2*l2+1, n3 = 2*l3+1, tot = n1*n2*n3;
        __shared__ float sCc[125];
        __shared__ cplxf sU1[25], sU2[25], sU3[25];
        __shared__ float sRe[125], sIm[125];
        __shared__ float4 sRed[256];

        for (int i = tid; i < tot; i += 256){
            int a = i / (n2*n3), b = (i / n3) % n2, c = i % n3;
            sCc[i] = su2_cgf(l1, l2, l3, a - l1, b - l2, c - l3);
        }
        if (tid == 0){ u_fillf(l1, sU1); u_fillf(l2, sU2); u_fillf(l3, sU3); }
        __syncthreads();

        for (int i = tid; i < tot; i += 256){
            int a = i / (n2*n3), b = (i / n3) % n2, c = i % n3;
            float re = 0, im = 0;
            for (int q1 = 0; q1 < n1; q1++)
            for (int q2 = 0; q2 < n2; q2++){
                cplxf u12 = cmulf(cconjf(sU1[a*n1 + q1]), cconjf(sU2[b*n2 + q2]));
                if (u12.re == 0.f && u12.im == 0.f) continue;
                for (int q3 = 0; q3 < n3; q3++){
                    float cc = sCc[q1*n2*n3 + q2*n3 + q3];
                    if (cc == 0.f) continue;
                    cplxf t = cmulf(u12, sU3[c*n3 + q3]);
                    re += t.re * cc; im += t.im * cc;
                }
            }
            sRe[i] = re; sIm[i] = im;
        }
        __syncthreads();

        float4 acc = make_float4(0.f, 0.f, 0.f, 0.f);
        if (tid < tot){
            float r = sRe[tid], m = sIm[tid];
            acc = make_float4(fabsf(r), fabsf(m), r*r, m*m);
        }
        sRed[tid] = acc; __syncthreads();
        for (int s = 128; s > 0; s >>= 1){
            if (tid < s){
                float4 a = sRed[tid], b = sRed[tid+s];
                sRed[tid] = make_float4(fmaxf(a.x,b.x), fmaxf(a.y,b.y), a.z+b.z, a.w+b.w);
            }
            __syncthreads();
        }
        float4 r0 = sRed[0];
        bool useIm = (r0.y > r0.x);
        float nrm = sqrtf(useIm ? r0.w : r0.z);
        if (nrm < 1e-12f) nrm = 1e-12f;
        if (tid < 125){
            float v = 0.f;
            if (tid < tot) v = (useIm ? sIm[tid] : sRe[tid]) / nrm;
            g_CG[p*125 + tid] = v;
        }

    } else if (bid == NPATH){
        __shared__ int cnt[BB], starts[BB];
        if (tid < BB) cnt[tid] = 0;
        __syncthreads();
        for (int i = tid; i < n; i += 256) atomicAdd(&cnt[batch[i]], 1);
        __syncthreads();
        if (tid == 0){ int s = 0; for (int b = 0; b < BB; b++){ starts[b] = s; s += cnt[b]; } }
        __syncthreads();
        for (int i = tid; i < n; i += 256){
            int b = batch[i];
            int pos = i - starts[b];
            g_slotOf[i] = (pos < MN) ? (b*MN + pos) : -1;
        }

    } else {
        int idx = (bid - NPATH - 1) * 256 + tid;
        const float s0  = rsqrtf(144.f * 16.f);
        const float s12 = rsqrtf(192.f * 16.f);
        if (idx < 13824){
            int u = idx / 96, r = idx % 96, f = r >> 1, o = r & 1;
            float acc = 0.f;
            #pragma unroll
            for (int k = 0; k < 16; k++) acc += Wo0[u*768 + k*48 + f] * Wt0[k*2 + o];
            g_Weff0[idx] = acc * s0;
        } else if (idx < 23040){
            int j = idx - 13824, u = j / 48, f = j % 48;
            float acc = 0.f;
            #pragma unroll
            for (int k = 0; k < 16; k++) acc += Wo1[u*768 + k*48 + f] * Wt1[k];
            g_Weff1[j] = acc * s12;
        } else if (idx < 32256){
            int j = idx - 23040, u = j / 48, f = j % 48;
            float acc = 0.f;
            #pragma unroll
            for (int k = 0; k < 16; k++) acc += Wo2[u*768 + k*48 + f] * Wt2[k];
            g_Weff2[j] = acc * s12;
        } else if (idx < 57600){
            int j = idx - 32256, p = j / 2304, r = j % 2304, v = r / 48, u = r % 48;
            g_tpwT[p*2304 + v*48 + u] = tpw[p*2304 + u*48 + v];
        }
    }
}

// ---------------- zero-fill (round-10 proven: 592 blocks, ~10.4 TB/s) ----------------
__global__ void __launch_bounds__(256) k_zero(float4* __restrict__ out, unsigned total4){
    const float4 z = make_float4(0.f, 0.f, 0.f, 0.f);
    unsigned stride = ZB * 256u;
    #pragma unroll 4
    for (unsigned i = blockIdx.x * 256u + threadIdx.x; i < total4; i += stride)
        out[i] = z;
}

// ---------------- fused per-node chain (round-12 proven, 43.3us w/ direct writes) ----------------
#define NT 1024
__global__ void __launch_bounds__(NT) k_node(const float* __restrict__ nf,
                                             const float* __restrict__ W0,
                                             const float* __restrict__ W1,
                                             const float* __restrict__ W2,
                                             float4* __restrict__ out, int n){
    int base = blockIdx.x * 2, tid = threadIdx.x;
    __shared__ float s_x[864];     // [nd][432]
    __shared__ float s_y[864];
    __shared__ float s_a[3360];    // [nd][1680]
    __shared__ float s_o[3360];
    __shared__ float s_g[960];     // [nd][480]

    const float sF = rsqrtf(48.f);
    int nn = (base + 2 <= n) ? 2 : (n - base);

    for (int i = tid; i < 864; i += NT)
        s_x[i] = (i < 432*nn) ? __ldg(nf + (size_t)base*432 + i) : 0.f;
    __syncthreads();

    // Phase 1: y[c*48+v] for both nodes; weight loaded once per (u,v)
    for (int i = tid; i < 432; i += NT){
        int c = i / 48, v = i % 48;
        const float* x0 = s_x;
        const float* x1 = s_x + 432;
        float a0=0.f,a1=0.f,a2=0.f,a3=0.f, b0=0.f,b1=0.f,b2=0.f,b3=0.f;
        if (c == 0){
            #pragma unroll
            for (int u = 0; u < 48; u += 4){
                float w0=__ldg(W0+u*48+v), w1=__ldg(W0+(u+1)*48+v), w2=__ldg(W0+(u+2)*48+v), w3=__ldg(W0+(u+3)*48+v);
                a0+=x0[u]*w0; a1+=x0[u+1]*w1; a2+=x0[u+2]*w2; a3+=x0[u+3]*w3;
                b0+=x1[u]*w0; b1+=x1[u+1]*w1; b2+=x1[u+2]*w2; b3+=x1[u+3]*w3;
            }
        } else if (c < 4){
            const int ii = c - 1;
            #pragma unroll
            for (int u = 0; u < 48; u += 4){
                float w0=__ldg(W1+u*48+v), w1=__ldg(W1+(u+1)*48+v), w2=__ldg(W1+(u+2)*48+v), w3=__ldg(W1+(u+3)*48+v);
                a0+=x0[48+u*3+ii]*w0; a1+=x0[48+(u+1)*3+ii]*w1; a2+=x0[48+(u+2)*3+ii]*w2; a3+=x0[48+(u+3)*3+ii]*w3;
                b0+=x1[48+u*3+ii]*w0; b1+=x1[48+(u+1)*3+ii]*w1; b2+=x1[48+(u+2)*3+ii]*w2; b3+=x1[48+(u+3)*3+ii]*w3;
            }
        } else {
            const int ii = c - 4;
            #pragma unroll
            for (int u = 0; u < 48; u += 4){
                float w0=__ldg(W2+u*48+v), w1=__ldg(W2+(u+1)*48+v), w2=__ldg(W2+(u+2)*48+v), w3=__ldg(W2+(u+3)*48+v);
                a0+=x0[192+u*5+ii]*w0; a1+=x0[192+(u+1)*5+ii]*w1; a2+=x0[192+(u+2)*5+ii]*w2; a3+=x0[192+(u+3)*5+ii]*w3;
                b0+=x1[192+u*5+ii]*w0; b1+=x1[192+(u+1)*5+ii]*w1; b2+=x1[192+(u+2)*5+ii]*w2; b3+=x1[192+(u+3)*5+ii]*w3;
            }
        }
        s_y[i]       = ((a0+a1)+(a2+a3)) * sF;
        s_y[432 + i] = ((b0+b1)+(b2+b3)) * sF;
    }
    __syncthreads();

    // Phase 2: a[j*48+u] for both nodes; coalesced weight loads reused 2x
    for (int i = tid; i < 1680; i += NT){
        int u = i % 48, j = i / 48;
        int p = c_j_p[j], c2 = c_j_c2[j];
        const float* y0 = s_y + c2*48;
        const float* y1 = s_y + 432 + c2*48;
        const float* wT = g_tpwT + p*2304 + u;
        float a0=0.f,a1=0.f,a2=0.f,a3=0.f, b0=0.f,b1=0.f,b2=0.f,b3=0.f;
        #pragma unroll
        for (int v = 0; v < 48; v += 4){
            float w0=__ldg(wT+v*48), w1=__ldg(wT+(v+1)*48), w2=__ldg(wT+(v+2)*48), w3=__ldg(wT+(v+3)*48);
            a0+=y0[v]*w0; a1+=y0[v+1]*w1; a2+=y0[v+2]*w2; a3+=y0[v+3]*w3;
            b0+=y1[v]*w0; b1+=y1[v+1]*w1; b2+=y1[v+2]*w2; b3+=y1[v+3]*w3;
        }
        s_a[i]        = ((a0+a1)+(a2+a3)) * sF;
        s_a[1680 + i] = ((b0+b1)+(b2+b3)) * sF;
    }
    __syncthreads();

    // Phase 3: CG contraction -> o (packed), both nodes (3360 items)
    for (int i = tid; i < 3360; i += NT){
        int nd = (i >= 1680);
        int ii = i - nd*1680;
        int u = ii % 48, os = ii / 48;
        int p = c_os_p[os], c3 = c_os_c3[os];
        int l1 = c_l1[p], l2 = c_l2[p];
        int n1 = 2*l1+1, n2 = 2*l2+1, n3 = 2*c_l3[p]+1;
        int cb1 = (l1 == 0) ? 0 : (l1 == 1) ? 1 : 4;
        int ao = c_aoff[p];
        const float* cg = g_CG + p*125 + c3;
        const float* yy = s_y + nd*432;
        const float* aa = s_a + nd*1680;
        float acc = 0.f;
        for (int m = 0; m < n1; m++){
            float ym = yy[(cb1 + m)*48 + u];
            for (int k = 0; k < n2; k++)
                acc += ym * aa[(ao + k)*48 + u] * __ldg(cg + (m*n2 + k)*n3);
        }
        s_o[nd*1680 + c_os_dst[os] + u] = acc;
    }
    __syncthreads();

    // Phase 4: g = o @ Weff, both nodes per thread (weights reused 2x)
    for (int i = tid; i < 480; i += NT){
        float a0=0.f,a1=0.f,a2=0.f,a3=0.f, b0=0.f,b1=0.f,b2=0.f,b3=0.f;
        if (i < 96){
            const float* o0 = s_o;
            const float* o1 = s_o + 1680;
            #pragma unroll
            for (int u = 0; u < 144; u += 4){
                float w0=__ldg(g_Weff0+u*96+i), w1=__ldg(g_Weff0+(u+1)*96+i), w2=__ldg(g_Weff0+(u+2)*96+i), w3=__ldg(g_Weff0+(u+3)*96+i);
                a0+=o0[u]*w0; a1+=o0[u+1]*w1; a2+=o0[u+2]*w2; a3+=o0[u+3]*w3;
                b0+=o1[u]*w0; b1+=o1[u+1]*w1; b2+=o1[u+2]*w2; b3+=o1[u+3]*w3;
            }
        } else if (i < 240){
            int j = i - 96, ii = j / 48, f = j % 48;
            const float* o0 = s_o + 144 + ii*192;
            const float* o1 = s_o + 1680 + 144 + ii*192;
            #pragma unroll
            for (int u = 0; u < 192; u += 4){
                float w0=__ldg(g_Weff1+u*48+f), w1=__ldg(g_Weff1+(u+1)*48+f), w2=__ldg(g_Weff1+(u+2)*48+f), w3=__ldg(g_Weff1+(u+3)*48+f);
                a0+=o0[u]*w0; a1+=o0[u+1]*w1; a2+=o0[u+2]*w2; a3+=o0[u+3]*w3;
                b0+=o1[u]*w0; b1+=o1[u+1]*w1; b2+=o1[u+2]*w2; b3+=o1[u+3]*w3;
            }
        } else {
            int j = i - 240, ii = j / 48, f = j % 48;
            const float* o0 = s_o + 720 + ii*192;
            const float* o1 = s_o + 1680 + 720 + ii*192;
            #pragma unroll
            for (int u = 0; u < 192; u += 4){
                float w0=__ldg(g_Weff2+u*48+f), w1=__ldg(g_Weff2+(u+1)*48+f), w2=__ldg(g_Weff2+(u+2)*48+f), w3=__ldg(g_Weff2+(u+3)*48+f);
                a0+=o0[u]*w0; a1+=o0[u+1]*w1; a2+=o0[u+2]*w2; a3+=o0[u+3]*w3;
                b0+=o1[u]*w0; b1+=o1[u+1]*w1; b2+=o1[u+2]*w2; b3+=o1[u+3]*w3;
            }
        }
        s_g[i]       = (a0+a1)+(a2+a3);
        s_g[480 + i] = (b0+b1)+(b2+b3);
    }
    __syncthreads();

    // Phase 5: assemble 4x4 M per (nd, f) and write diagonals DIRECTLY into zeroed d_out
    if (tid < 96){
        int nd = tid / 48, f = tid % 48;
        if (nd < nn){
            int slot = g_slotOf[base + nd];
            if (slot >= 0){
                const float* g = s_g + nd*480;
                float a0 = g[f*2 + 0], a1 = g[f*2 + 1];
                float v0 = g[96 + f], v1 = g[144 + f], v2 = g[192 + f];
                float dd[5];
                #pragma unroll
                for (int m = 0; m < 5; m++) dd[m] = g[240 + m*48 + f];
                const float* cg112 = g_CG + 5*125;   // path 5 = (1,1,2), (3,3,5)
                const float is3 = 0.57735026918962576f;
                float S[3][3];
                #pragma unroll
                for (int i = 0; i < 3; i++)
                #pragma unroll
                for (int j = 0; j < 3; j++){
                    float acc = (i == j) ? a1 * is3 : 0.f;
                    #pragma unroll
                    for (int m = 0; m < 5; m++) acc += dd[m] * cg112[i*15 + j*5 + m];
                    S[i][j] = acc;
                }
                float4 r0 = make_float4(a0, v0,      v1,      v2);
                float4 r1 = make_float4(v0, S[0][0], S[0][1], S[0][2]);
                float4 r2 = make_float4(v1, S[1][0], S[1][1], S[1][2]);
                float4 r3 = make_float4(v2, S[2][0], S[2][1], S[2][2]);
                // out float4 index: ((slot*PP + pp)*DD + f*4 + r)*48 + f
                #pragma unroll
                for (int pp = 0; pp < PP; pp++){
                    size_t b4 = (((size_t)slot*PP + pp)*DD + f*4)*48 + f;
                    out[b4]        = r0;
                    out[b4 + 48]   = r1;
                    out[b4 + 96]   = r2;
                    out[b4 + 144]  = r3;
                }
            }
        }
    }
}

// ---------------- launch ----------------
extern "C" void kernel_launch(void* const* d_in, const int* in_sizes, int n_in,
                              void* d_out, int out_size){
    const float* node_feats = (const float*)d_in[0];
    const float* W_lin0     = (const float*)d_in[1];
    const float* W_lin1     = (const float*)d_in[2];
    const float* W_lin2     = (const float*)d_in[3];
    const float* tp_w       = (const float*)d_in[4];
    const float* W_out0     = (const float*)d_in[5];
    const float* W_out1     = (const float*)d_in[6];
    const float* W_out2     = (const float*)d_in[7];
    const float* Wt0        = (const float*)d_in[8];
    const float* Wt1        = (const float*)d_in[9];
    const float* Wt2        = (const float*)d_in[10];
    const int*   batch      = (const int*)  d_in[11];

    int n  = in_sizes[0] / 432;
    int MN = out_size / (BB * PP * DD * DD);
    unsigned total4 = (unsigned)(out_size / 4);

    // serial chain of individually-measured best pieces
    k_prep<<<NPATH + 1 + 225, 256>>>(W_out0, W_out1, W_out2, Wt0, Wt1, Wt2, tp_w, batch, n, MN);
    k_zero<<<ZB, 256>>>((float4*)d_out, total4);
    k_node<<<(n + 1) / 2, NT>>>(node_feats, W_lin0, W_lin1, W_lin2, (float4*)d_out, n);
}

// round 14
// speedup vs baseline: 1.1563x; 1.1563x over previous
#include <cuda_runtime.h>

// ---------------- constants ----------------
#define FM     48
#define NPATH  11
#define NMAX   1024
#define BB     8
#define PP     2
#define DD     192
#define ZB     592   // zero-fill blocks

// ---------------- device scratch ----------------
__device__ float  g_CG[NPATH * 125];
__device__ float  g_Weff0[144 * 96];          // [u][i]   (lanes i contiguous)
__device__ float  g_Weff1[192 * 48];          // [u][f]
__device__ float  g_Weff2[192 * 48];
__device__ float  g_tpwT[NPATH * 2304];       // [p][v][u] (lanes u contiguous)
__device__ float4 g_M4[NMAX * 48 * 4];        // per node/f: 4 rows of float4
__device__ int    g_slotOf[NMAX];             // node -> b*MN+pos (or -1)

// path tables
__constant__ int c_l1[NPATH]   = {0,0,0,1,1,1,1,2,2,2,2};
__constant__ int c_l2[NPATH]   = {0,1,2,0,1,1,2,0,1,2,2};
__constant__ int c_l3[NPATH]   = {0,1,2,1,0,2,1,2,1,0,2};
__constant__ int c_aoff[NPATH] = {0,1,4,9,10,13,16,21,22,25,30};

// a-stage tables: 35 (path,k) slots
__constant__ int c_j_p[35]  = {0, 1,1,1, 2,2,2,2,2, 3, 4,4,4, 5,5,5, 6,6,6,6,6, 7, 8,8,8, 9,9,9,9,9, 10,10,10,10,10};
__constant__ int c_j_c2[35] = {0, 1,2,3, 4,5,6,7,8, 0, 1,2,3, 1,2,3, 4,5,6,7,8, 0, 1,2,3, 4,5,6,7,8, 4,5,6,7,8};

// o-stage tables: 35 (path,c3) outputs; dst = offset in packed o[1680]
__constant__ int c_os_p[35]  = {0, 1,1,1, 2,2,2,2,2, 3,3,3, 4, 5,5,5,5,5, 6,6,6, 7,7,7,7,7, 8,8,8, 9, 10,10,10,10,10};
__constant__ int c_os_c3[35] = {0, 0,1,2, 0,1,2,3,4, 0,1,2, 0, 0,1,2,3,4, 0,1,2, 0,1,2,3,4, 0,1,2, 0, 0,1,2,3,4};
__constant__ int c_os_dst[35]= {0, 144,336,528, 720,912,1104,1296,1488, 192,384,576, 48,
                                768,960,1152,1344,1536, 240,432,624, 816,1008,1200,1392,1584,
                                288,480,672, 96, 864,1056,1248,1440,1632};

// ---------------- CG helpers (fp32, factorials <= 5040 exact) ----------------
struct cplxf { float re, im; };
__device__ __forceinline__ cplxf cmulf(cplxf a, cplxf b){ return {a.re*b.re - a.im*b.im, a.re*b.im + a.im*b.re}; }
__device__ __forceinline__ cplxf cconjf(cplxf a){ return {a.re, -a.im}; }
__device__ float f_fact(int x){ float r = 1.f; for (int i = 2; i <= x; i++) r *= (float)i; return r; }

__device__ float su2_cgf(int j1,int j2,int j3,int m1,int m2,int m3){
    if (m1 + m2 != m3) return 0.f;
    float pre = sqrtf((float)(2*j3+1) * f_fact(j3+j1-j2) * f_fact(j3-j1+j2) * f_fact(j1+j2-j3)
                      / f_fact(j1+j2+j3+1));
    pre *= sqrtf(f_fact(j3+m3)*f_fact(j3-m3)*f_fact(j1-m1)*f_fact(j1+m1)*f_fact(j2-m2)*f_fact(j2+m2));
    float s = 0.f;
    for (int v = 0; v <= j1 + j2 - j3; v++){
        int a1 = j1+j2-j3-v, a2 = j1-m1-v, a3 = j2+m2-v, a4 = j3-j2+m1+v, a5 = j3-j1-m2+v;
        if (a1 < 0 || a2 < 0 || a3 < 0 || a4 < 0 || a5 < 0) continue;
        float den = f_fact(v)*f_fact(a1)*f_fact(a2)*f_fact(a3)*f_fact(a4)*f_fact(a5);
        s += ((v & 1) ? -1.f : 1.f) / den;
    }
    return pre * s;
}

__device__ void u_fillf(int l, cplxf* U){
    int n = 2*l + 1;
    for (int i = 0; i < n*n; i++) U[i] = {0.f, 0.f};
    float s2 = sqrtf(0.5f);
    for (int m = -l; m <= l; m++){
        int a = l + m;
        if (m > 0){
            U[a*n + (l+m)] = {((m & 1) ? -1.f : 1.f) * s2, 0.f};
            U[a*n + (l-m)] = {s2, 0.f};
        } else if (m == 0){
            U[a*n + l] = {1.f, 0.f};
        } else {
            int mm = -m;
            U[a*n + (l+m)] = {0.f, s2};
            U[a*n + (l-m)] = {0.f, -(((mm & 1) ? -1.f : 1.f)) * s2};
        }
    }
}

// ---------------- prep: blocks 0..10 CG | 11 setup | 12.. weff+transpose ----------------
__global__ void __launch_bounds__(256) k_prep(const float* __restrict__ Wo0, const float* __restrict__ Wo1,
                                              const float* __restrict__ Wo2, const float* __restrict__ Wt0,
                                              const float* __restrict__ Wt1, const float* __restrict__ Wt2,
                                              const float* __restrict__ tpw, const int* __restrict__ batch,
                                              int n, int MN){
    int bid = blockIdx.x, tid = threadIdx.x;

    if (bid < NPATH){
        int p = bid;
        int l1 = c_l1[p], l2 = c_l2[p], l3 = c_l3[p];
        int n1 = 2*l1+1, n2 = 2*l2+1, n3 = 2*l3+1, tot = n1*n2*n3;
        __shared__ float sCc[125];
        __shared__ cplxf sU1[25], sU2[25], sU3[25];
        __shared__ float sRe[125], sIm[125];
        __shared__ float4 sRed[256];

        for (int i = tid; i < tot; i += 256){
            int a = i / (n2*n3), b = (i / n3) % n2, c = i % n3;
            sCc[i] = su2_cgf(l1, l2, l3, a - l1, b - l2, c - l3);
        }
        if (tid == 0){ u_fillf(l1, sU1); u_fillf(l2, sU2); u_fillf(l3, sU3); }
        __syncthreads();

        for (int i = tid; i < tot; i += 256){
            int a = i / (n2*n3), b = (i / n3) % n2, c = i % n3;
            float re = 0, im = 0;
            for (int q1 = 0; q1 < n1; q1++)
            for (int q2 = 0; q2 < n2; q2++){
                cplxf u12 = cmulf(cconjf(sU1[a*n1 + q1]), cconjf(sU2[b*n2 + q2]));
                if (u12.re == 0.f && u12.im == 0.f) continue;
                for (int q3 = 0; q3 < n3; q3++){
                    float cc = sCc[q1*n2*n3 + q2*n3 + q3];
                    if (cc == 0.f) continue;
                    cplxf t = cmulf(u12, sU3[c*n3 + q3]);
                    re += t.re * cc; im += t.im * cc;
                }
            }
            sRe[i] = re; sIm[i] = im;
        }
        __syncthreads();

        float4 acc = make_float4(0.f, 0.f, 0.f, 0.f);
        if (tid < tot){
            float r = sRe[tid], m = sIm[tid];
            acc = make_float4(fabsf(r), fabsf(m), r*r, m*m);
        }
        sRed[tid] = acc; __syncthreads();
        for (int s = 128; s > 0; s >>= 1){
            if (tid < s){
                float4 a = sRed[tid], b = sRed[tid+s];
                sRed[tid] = make_float4(fmaxf(a.x,b.x), fmaxf(a.y,b.y), a.z+b.z, a.w+b.w);
            }
            __syncthreads();
        }
        float4 r0 = sRed[0];
        bool useIm = (r0.y > r0.x);
        float nrm = sqrtf(useIm ? r0.w : r0.z);
        if (nrm < 1e-12f) nrm = 1e-12f;
        if (tid < 125){
            float v = 0.f;
            if (tid < tot) v = (useIm ? sIm[tid] : sRe[tid]) / nrm;
            g_CG[p*125 + tid] = v;
        }

    } else if (bid == NPATH){
        __shared__ int cnt[BB], starts[BB];
        if (tid < BB) cnt[tid] = 0;
        __syncthreads();
        for (int i = tid; i < n; i += 256) atomicAdd(&cnt[batch[i]], 1);
        __syncthreads();
        if (tid == 0){ int s = 0; for (int b = 0; b < BB; b++){ starts[b] = s; s += cnt[b]; } }
        __syncthreads();
        for (int i = tid; i < n; i += 256){
            int b = batch[i];
            int pos = i - starts[b];
            g_slotOf[i] = (pos < MN) ? (b*MN + pos) : -1;
        }

    } else {
        int idx = (bid - NPATH - 1) * 256 + tid;
        const float s0  = rsqrtf(144.f * 16.f);
        const float s12 = rsqrtf(192.f * 16.f);
        if (idx < 13824){
            int u = idx / 96, r = idx % 96, f = r >> 1, o = r & 1;
            float acc = 0.f;
            #pragma unroll
            for (int k = 0; k < 16; k++) acc += Wo0[u*768 + k*48 + f] * Wt0[k*2 + o];
            g_Weff0[idx] = acc * s0;
        } else if (idx < 23040){
            int j = idx - 13824, u = j / 48, f = j % 48;
            float acc = 0.f;
            #pragma unroll
            for (int k = 0; k < 16; k++) acc += Wo1[u*768 + k*48 + f] * Wt1[k];
            g_Weff1[j] = acc * s12;
        } else if (idx < 32256){
            int j = idx - 23040, u = j / 48, f = j % 48;
            float acc = 0.f;
            #pragma unroll
            for (int k = 0; k < 16; k++) acc += Wo2[u*768 + k*48 + f] * Wt2[k];
            g_Weff2[j] = acc * s12;
        } else if (idx < 57600){
            int j = idx - 32256, p = j / 2304, r = j % 2304, v = r / 48, u = r % 48;
            g_tpwT[p*2304 + v*48 + u] = tpw[p*2304 + u*48 + v];
        }
    }
}

// ---------------- zero-fill: streaming stores (evict-first, don't thrash L2) ----------------
__global__ void __launch_bounds__(256) k_zero(float4* __restrict__ out, unsigned total4){
    const float4 z = make_float4(0.f, 0.f, 0.f, 0.f);
    unsigned stride = ZB * 256u;
    #pragma unroll 4
    for (unsigned i = blockIdx.x * 256u + threadIdx.x; i < total4; i += stride)
        __stcs(out + i, z);
}

// ---------------- fused per-node chain: 4 nodes/block via 2 passes of 2 (L1-hot weights) ----------------
#define NT 1024
__global__ void __launch_bounds__(NT) k_node(const float* __restrict__ nf,
                                             const float* __restrict__ W0,
                                             const float* __restrict__ W1,
                                             const float* __restrict__ W2,
                                             int n){
    int tid = threadIdx.x;
    __shared__ float s_x[864];     // [nd][432]
    __shared__ float s_y[864];
    __shared__ float s_a[3360];    // [nd][1680]
    __shared__ float s_o[3360];
    __shared__ float s_g[960];     // [nd][480]

    const float sF = rsqrtf(48.f);

    for (int pass = 0; pass < 2; pass++){
        int base = blockIdx.x * 4 + pass * 2;
        if (base >= n) return;
        int nn = (base + 2 <= n) ? 2 : (n - base);

        for (int i = tid; i < 864; i += NT)
            s_x[i] = (i < 432*nn) ? __ldg(nf + (size_t)base*432 + i) : 0.f;
        __syncthreads();

        // Phase 1: y[c*48+v] for both nodes; weight loaded once per (u,v)
        for (int i = tid; i < 432; i += NT){
            int c = i / 48, v = i % 48;
            const float* x0 = s_x;
            const float* x1 = s_x + 432;
            float a0=0.f,a1=0.f,a2=0.f,a3=0.f, b0=0.f,b1=0.f,b2=0.f,b3=0.f;
            if (c == 0){
                #pragma unroll
                for (int u = 0; u < 48; u += 4){
                    float w0=__ldg(W0+u*48+v), w1=__ldg(W0+(u+1)*48+v), w2=__ldg(W0+(u+2)*48+v), w3=__ldg(W0+(u+3)*48+v);
                    a0+=x0[u]*w0; a1+=x0[u+1]*w1; a2+=x0[u+2]*w2; a3+=x0[u+3]*w3;
                    b0+=x1[u]*w0; b1+=x1[u+1]*w1; b2+=x1[u+2]*w2; b3+=x1[u+3]*w3;
                }
            } else if (c < 4){
                const int ii = c - 1;
                #pragma unroll
                for (int u = 0; u < 48; u += 4){
                    float w0=__ldg(W1+u*48+v), w1=__ldg(W1+(u+1)*48+v), w2=__ldg(W1+(u+2)*48+v), w3=__ldg(W1+(u+3)*48+v);
                    a0+=x0[48+u*3+ii]*w0; a1+=x0[48+(u+1)*3+ii]*w1; a2+=x0[48+(u+2)*3+ii]*w2; a3+=x0[48+(u+3)*3+ii]*w3;
                    b0+=x1[48+u*3+ii]*w0; b1+=x1[48+(u+1)*3+ii]*w1; b2+=x1[48+(u+2)*3+ii]*w2; b3+=x1[48+(u+3)*3+ii]*w3;
                }
            } else {
                const int ii = c - 4;
                #pragma unroll
                for (int u = 0; u < 48; u += 4){
                    float w0=__ldg(W2+u*48+v), w1=__ldg(W2+(u+1)*48+v), w2=__ldg(W2+(u+2)*48+v), w3=__ldg(W2+(u+3)*48+v);
                    a0+=x0[192+u*5+ii]*w0; a1+=x0[192+(u+1)*5+ii]*w1; a2+=x0[192+(u+2)*5+ii]*w2; a3+=x0[192+(u+3)*5+ii]*w3;
                    b0+=x1[192+u*5+ii]*w0; b1+=x1[192+(u+1)*5+ii]*w1; b2+=x1[192+(u+2)*5+ii]*w2; b3+=x1[192+(u+3)*5+ii]*w3;
                }
            }
            s_y[i]       = ((a0+a1)+(a2+a3)) * sF;
            s_y[432 + i] = ((b0+b1)+(b2+b3)) * sF;
        }
        __syncthreads();

        // Phase 2: a[j*48+u] for both nodes; coalesced weight loads reused 2x
        for (int i = tid; i < 1680; i += NT){
            int u = i % 48, j = i / 48;
            int p = c_j_p[j], c2 = c_j_c2[j];
            const float* y0 = s_y + c2*48;
            const float* y1 = s_y + 432 + c2*48;
            const float* wT = g_tpwT + p*2304 + u;
            float a0=0.f,a1=0.f,a2=0.f,a3=0.f, b0=0.f,b1=0.f,b2=0.f,b3=0.f;
            #pragma unroll
            for (int v = 0; v < 48; v += 4){
                float w0=__ldg(wT+v*48), w1=__ldg(wT+(v+1)*48), w2=__ldg(wT+(v+2)*48), w3=__ldg(wT+(v+3)*48);
                a0+=y0[v]*w0; a1+=y0[v+1]*w1; a2+=y0[v+2]*w2; a3+=y0[v+3]*w3;
                b0+=y1[v]*w0; b1+=y1[v+1]*w1; b2+=y1[v+2]*w2; b3+=y1[v+3]*w3;
            }
            s_a[i]        = ((a0+a1)+(a2+a3)) * sF;
            s_a[1680 + i] = ((b0+b1)+(b2+b3)) * sF;
        }
        __syncthreads();

        // Phase 3: CG contraction -> o (packed), both nodes (3360 items)
        for (int i = tid; i < 3360; i += NT){
            int nd = (i >= 1680);
            int ii = i - nd*1680;
            int u = ii % 48, os = ii / 48;
            int p = c_os_p[os], c3 = c_os_c3[os];
            int l1 = c_l1[p], l2 = c_l2[p];
            int n1 = 2*l1+1, n2 = 2*l2+1, n3 = 2*c_l3[p]+1;
            int cb1 = (l1 == 0) ? 0 : (l1 == 1) ? 1 : 4;
            int ao = c_aoff[p];
            const float* cg = g_CG + p*125 + c3;
            const float* yy = s_y + nd*432;
            const float* aa = s_a + nd*1680;
            float acc = 0.f;
            for (int m = 0; m < n1; m++){
                float ym = yy[(cb1 + m)*48 + u];
                for (int k = 0; k < n2; k++)
                    acc += ym * aa[(ao + k)*48 + u] * __ldg(cg + (m*n2 + k)*n3);
            }
            s_o[nd*1680 + c_os_dst[os] + u] = acc;
        }
        __syncthreads();

        // Phase 4: g = o @ Weff, both nodes per thread (weights reused 2x)
        for (int i = tid; i < 480; i += NT){
            float a0=0.f,a1=0.f,a2=0.f,a3=0.f, b0=0.f,b1=0.f,b2=0.f,b3=0.f;
            if (i < 96){
                const float* o0 = s_o;
                const float* o1 = s_o + 1680;
                #pragma unroll
                for (int u = 0; u < 144; u += 4){
                    float w0=__ldg(g_Weff0+u*96+i), w1=__ldg(g_Weff0+(u+1)*96+i), w2=__ldg(g_Weff0+(u+2)*96+i), w3=__ldg(g_Weff0+(u+3)*96+i);
                    a0+=o0[u]*w0; a1+=o0[u+1]*w1; a2+=o0[u+2]*w2; a3+=o0[u+3]*w3;
                    b0+=o1[u]*w0; b1+=o1[u+1]*w1; b2+=o1[u+2]*w2; b3+=o1[u+3]*w3;
                }
            } else if (i < 240){
                int j = i - 96, ii = j / 48, f = j % 48;
                const float* o0 = s_o + 144 + ii*192;
                const float* o1 = s_o + 1680 + 144 + ii*192;
                #pragma unroll
                for (int u = 0; u < 192; u += 4){
                    float w0=__ldg(g_Weff1+u*48+f), w1=__ldg(g_Weff1+(u+1)*48+f), w2=__ldg(g_Weff1+(u+2)*48+f), w3=__ldg(g_Weff1+(u+3)*48+f);
                    a0+=o0[u]*w0; a1+=o0[u+1]*w1; a2+=o0[u+2]*w2; a3+=o0[u+3]*w3;
                    b0+=o1[u]*w0; b1+=o1[u+1]*w1; b2+=o1[u+2]*w2; b3+=o1[u+3]*w3;
                }
            } else {
                int j = i - 240, ii = j / 48, f = j % 48;
                const float* o0 = s_o + 720 + ii*192;
                const float* o1 = s_o + 1680 + 720 + ii*192;
                #pragma unroll
                for (int u = 0; u < 192; u += 4){
                    float w0=__ldg(g_Weff2+u*48+f), w1=__ldg(g_Weff2+(u+1)*48+f), w2=__ldg(g_Weff2+(u+2)*48+f), w3=__ldg(g_Weff2+(u+3)*48+f);
                    a0+=o0[u]*w0; a1+=o0[u+1]*w1; a2+=o0[u+2]*w2; a3+=o0[u+3]*w3;
                    b0+=o1[u]*w0; b1+=o1[u+1]*w1; b2+=o1[u+2]*w2; b3+=o1[u+3]*w3;
                }
            }
            s_g[i]       = (a0+a1)+(a2+a3);
            s_g[480 + i] = (b0+b1)+(b2+b3);
        }
        __syncthreads();

        // Phase 5: assemble 4x4 M per (nd, f) -> g_M4
        if (tid < 96){
            int nd = tid / 48, f = tid % 48;
            if (nd < nn){
                const float* g = s_g + nd*480;
                float a0 = g[f*2 + 0], a1 = g[f*2 + 1];
                float v0 = g[96 + f], v1 = g[144 + f], v2 = g[192 + f];
                float dd[5];
                #pragma unroll
                for (int m = 0; m < 5; m++) dd[m] = g[240 + m*48 + f];
                const float* cg112 = g_CG + 5*125;   // path 5 = (1,1,2), (3,3,5)
                const float is3 = 0.57735026918962576f;
                float S[3][3];
                #pragma unroll
                for (int i = 0; i < 3; i++)
                #pragma unroll
                for (int j = 0; j < 3; j++){
                    float acc = (i == j) ? a1 * is3 : 0.f;
                    #pragma unroll
                    for (int m = 0; m < 5; m++) acc += dd[m] * cg112[i*15 + j*5 + m];
                    S[i][j] = acc;
                }
                float4* mout = g_M4 + ((size_t)(base + nd)*48 + f)*4;
                mout[0] = make_float4(a0, v0,      v1,      v2);
                mout[1] = make_float4(v0, S[0][0], S[0][1], S[0][2]);
                mout[2] = make_float4(v1, S[1][0], S[1][1], S[1][2]);
                mout[3] = make_float4(v2, S[2][0], S[2][1], S[2][2]);
            }
        }
        __syncthreads();
    }
}

// ---------------- scatter diagonals into zeroed output ----------------
__global__ void __launch_bounds__(192) k_scatter(float4* __restrict__ out){
    int node = blockIdx.x, t = threadIdx.x;   // 192 = 48 f * 4 rows
    int slot = g_slotOf[node];
    if (slot < 0) return;
    int f = t >> 2, r = t & 3;
    float4 v = g_M4[((size_t)node*48 + f)*4 + r];
    size_t base = (((size_t)slot*PP)*DD + f*4 + r)*48 + f;
    out[base] = v;
    out[base + (size_t)DD*48] = v;   // second P slice
}

// ---------------- launch ----------------
extern "C" void kernel_launch(void* const* d_in, const int* in_sizes, int n_in,
                              void* d_out, int out_size){
    const float* node_feats = (const float*)d_in[0];
    const float* W_lin0     = (const float*)d_in[1];
    const float* W_lin1     = (const float*)d_in[2];
    const float* W_lin2     = (const float*)d_in[3];
    const float* tp_w       = (const float*)d_in[4];
    const float* W_out0     = (const float*)d_in[5];
    const float* W_out1     = (const float*)d_in[6];
    const float* W_out2     = (const float*)d_in[7];
    const float* Wt0        = (const float*)d_in[8];
    const float* Wt1        = (const float*)d_in[9];
    const float* Wt2        = (const float*)d_in[10];
    const int*   batch      = (const int*)  d_in[11];

    int n  = in_sizes[0] / 432;
    int MN = out_size / (BB * PP * DD * DD);
    unsigned total4 = (unsigned)(out_size / 4);

    // Round-10 fork structure (only structure that showed real overlap):
    // s2: streaming zero of d_out; main: prep -> node -> g_M4; join; scatter.
    cudaStream_t s2;
    cudaStreamCreateWithFlags(&s2, cudaStreamNonBlocking);
    cudaEvent_t evF, evJ;
    cudaEventCreateWithFlags(&evF, cudaEventDisableTiming);
    cudaEventCreateWithFlags(&evJ, cudaEventDisableTiming);

    cudaEventRecord(evF, 0);
    cudaStreamWaitEvent(s2, evF, 0);

    k_zero<<<ZB, 256, 0, s2>>>((float4*)d_out, total4);
    cudaEventRecord(evJ, s2);

    k_prep<<<NPATH + 1 + 225, 256>>>(W_out0, W_out1, W_out2, Wt0, Wt1, Wt2, tp_w, batch, n, MN);
    k_node<<<(n + 3) / 4, NT>>>(node_feats, W_lin0, W_lin1, W_lin2, n);

    cudaStreamWaitEvent(0, evJ, 0);
    k_scatter<<<n, 192>>>((float4*)d_out);

    cudaEventDestroy(evF);
    cudaEventDestroy(evJ);
    cudaStreamDestroy(s2);
}

// round 15
// speedup vs baseline: 1.2445x; 1.0763x over previous
#include <cuda_runtime.h>

// ---------------- constants ----------------
#define FM     48
#define NPATH  11
#define NMAX   1024
#define BB     8
#define PP     2
#define DD     192
#define ZB     592   // zero-fill blocks

// ---------------- device scratch ----------------
__device__ float  g_CG[NPATH * 125];
__device__ float  g_Weff0[144 * 96];          // [u][i]   (lanes i contiguous)
__device__ float  g_Weff1[192 * 48];          // [u][f]
__device__ float  g_Weff2[192 * 48];
__device__ float  g_tpwT[NPATH * 2304];       // [p][v][u] (lanes u contiguous)
__device__ int    g_slotOf[NMAX];             // node -> b*MN+pos (or -1)

// path tables
__constant__ int c_l1[NPATH]   = {0,0,0,1,1,1,1,2,2,2,2};
__constant__ int c_l2[NPATH]   = {0,1,2,0,1,1,2,0,1,2,2};
__constant__ int c_l3[NPATH]   = {0,1,2,1,0,2,1,2,1,0,2};
__constant__ int c_aoff[NPATH] = {0,1,4,9,10,13,16,21,22,25,30};

// a-stage tables: 35 (path,k) slots
__constant__ int c_j_p[35]  = {0, 1,1,1, 2,2,2,2,2, 3, 4,4,4, 5,5,5, 6,6,6,6,6, 7, 8,8,8, 9,9,9,9,9, 10,10,10,10,10};
__constant__ int c_j_c2[35] = {0, 1,2,3, 4,5,6,7,8, 0, 1,2,3, 1,2,3, 4,5,6,7,8, 0, 1,2,3, 4,5,6,7,8, 4,5,6,7,8};

// o-stage tables: 35 (path,c3) outputs; dst = offset in packed o[1680]
__constant__ int c_os_p[35]  = {0, 1,1,1, 2,2,2,2,2, 3,3,3, 4, 5,5,5,5,5, 6,6,6, 7,7,7,7,7, 8,8,8, 9, 10,10,10,10,10};
__constant__ int c_os_c3[35] = {0, 0,1,2, 0,1,2,3,4, 0,1,2, 0, 0,1,2,3,4, 0,1,2, 0,1,2,3,4, 0,1,2, 0, 0,1,2,3,4};
__constant__ int c_os_dst[35]= {0, 144,336,528, 720,912,1104,1296,1488, 192,384,576, 48,
                                768,960,1152,1344,1536, 240,432,624, 816,1008,1200,1392,1584,
                                288,480,672, 96, 864,1056,1248,1440,1632};

// ---------------- CG helpers (fp32, factorials <= 5040 exact) ----------------
struct cplxf { float re, im; };
__device__ __forceinline__ cplxf cmulf(cplxf a, cplxf b){ return {a.re*b.re - a.im*b.im, a.re*b.im + a.im*b.re}; }
__device__ __forceinline__ cplxf cconjf(cplxf a){ return {a.re, -a.im}; }
__device__ float f_fact(int x){ float r = 1.f; for (int i = 2; i <= x; i++) r *= (float)i; return r; }

__device__ float su2_cgf(int j1,int j2,int j3,int m1,int m2,int m3){
    if (m1 + m2 != m3) return 0.f;
    float pre = sqrtf((float)(2*j3+1) * f_fact(j3+j1-j2) * f_fact(j3-j1+j2) * f_fact(j1+j2-j3)
                      / f_fact(j1+j2+j3+1));
    pre *= sqrtf(f_fact(j3+m3)*f_fact(j3-m3)*f_fact(j1-m1)*f_fact(j1+m1)*f_fact(j2-m2)*f_fact(j2+m2));
    float s = 0.f;
    for (int v = 0; v <= j1 + j2 - j3; v++){
        int a1 = j1+j2-j3-v, a2 = j1-m1-v, a3 = j2+m2-v, a4 = j3-j2+m1+v, a5 = j3-j1-m2+v;
        if (a1 < 0 || a2 < 0 || a3 < 0 || a4 < 0 || a5 < 0) continue;
        float den = f_fact(v)*f_fact(a1)*f_fact(a2)*f_fact(a3)*f_fact(a4)*f_fact(a5);
        s += ((v & 1) ? -1.f : 1.f) / den;
    }
    return pre * s;
}

__device__ void u_fillf(int l, cplxf* U){
    int n = 2*l + 1;
    for (int i = 0; i < n*n; i++) U[i] = {0.f, 0.f};
    float s2 = sqrtf(0.5f);
    for (int m = -l; m <= l; m++){
        int a = l + m;
        if (m > 0){
            U[a*n + (l+m)] = {((m & 1) ? -1.f : 1.f) * s2, 0.f};
            U[a*n + (l-m)] = {s2, 0.f};
        } else if (m == 0){
            U[a*n + l] = {1.f, 0.f};
        } else {
            int mm = -m;
            U[a*n + (l+m)] = {0.f, s2};
            U[a*n + (l-m)] = {0.f, -(((mm & 1) ? -1.f : 1.f)) * s2};
        }
    }
}

// ---------------- prep: blocks 0..10 CG | 11 setup | 12.. weff+transpose ----------------
__global__ void __launch_bounds__(256) k_prep(const float* __restrict__ Wo0, const float* __restrict__ Wo1,
                                              const float* __restrict__ Wo2, const float* __restrict__ Wt0,
                                              const float* __restrict__ Wt1, const float* __restrict__ Wt2,
                                              const float* __restrict__ tpw, const int* __restrict__ batch,
                                              int n, int MN){
    int bid = blockIdx.x, tid = threadIdx.x;

    if (bid < NPATH){
        int p = bid;
        int l1 = c_l1[p], l2 = c_l2[p], l3 = c_l3[p];
        int n1 = 2*l1+1, n2 = 2*l2+1, n3 = 2*l3+1, tot = n1*n2*n3;
        __shared__ float sCc[125];
        __shared__ cplxf sU1[25], sU2[25], sU3[25];
        __shared__ float sRe[125], sIm[125];
        __shared__ float4 sRed[256];

        for (int i = tid; i < tot; i += 256){
            int a = i / (n2*n3), b = (i / n3) % n2, c = i % n3;
            sCc[i] = su2_cgf(l1, l2, l3, a - l1, b - l2, c - l3);
        }
        if (tid == 0){ u_fillf(l1, sU1); u_fillf(l2, sU2); u_fillf(l3, sU3); }
        __syncthreads();

        for (int i = tid; i < tot; i += 256){
            int a = i / (n2*n3), b = (i / n3) % n2, c = i % n3;
            float re = 0, im = 0;
            for (int q1 = 0; q1 < n1; q1++)
            for (int q2 = 0; q2 < n2; q2++){
                cplxf u12 = cmulf(cconjf(sU1[a*n1 + q1]), cconjf(sU2[b*n2 + q2]));
                if (u12.re == 0.f && u12.im == 0.f) continue;
                for (int q3 = 0; q3 < n3; q3++){
                    float cc = sCc[q1*n2*n3 + q2*n3 + q3];
                    if (cc == 0.f) continue;
                    cplxf t = cmulf(u12, sU3[c*n3 + q3]);
                    re += t.re * cc; im += t.im * cc;
                }
            }
            sRe[i] = re; sIm[i] = im;
        }
        __syncthreads();

        float4 acc = make_float4(0.f, 0.f, 0.f, 0.f);
        if (tid < tot){
            float r = sRe[tid], m = sIm[tid];
            acc = make_float4(fabsf(r), fabsf(m), r*r, m*m);
        }
        sRed[tid] = acc; __syncthreads();
        for (int s = 128; s > 0; s >>= 1){
            if (tid < s){
                float4 a = sRed[tid], b = sRed[tid+s];
                sRed[tid] = make_float4(fmaxf(a.x,b.x), fmaxf(a.y,b.y), a.z+b.z, a.w+b.w);
            }
            __syncthreads();
        }
        float4 r0 = sRed[0];
        bool useIm = (r0.y > r0.x);
        float nrm = sqrtf(useIm ? r0.w : r0.z);
        if (nrm < 1e-12f) nrm = 1e-12f;
        if (tid < 125){
            float v = 0.f;
            if (tid < tot) v = (useIm ? sIm[tid] : sRe[tid]) / nrm;
            g_CG[p*125 + tid] = v;
        }

    } else if (bid == NPATH){
        __shared__ int cnt[BB], starts[BB];
        if (tid < BB) cnt[tid] = 0;
        __syncthreads();
        for (int i = tid; i < n; i += 256) atomicAdd(&cnt[batch[i]], 1);
        __syncthreads();
        if (tid == 0){ int s = 0; for (int b = 0; b < BB; b++){ starts[b] = s; s += cnt[b]; } }
        __syncthreads();
        for (int i = tid; i < n; i += 256){
            int b = batch[i];
            int pos = i - starts[b];
            g_slotOf[i] = (pos < MN) ? (b*MN + pos) : -1;
        }

    } else {
        int idx = (bid - NPATH - 1) * 256 + tid;
        const float s0  = rsqrtf(144.f * 16.f);
        const float s12 = rsqrtf(192.f * 16.f);
        if (idx < 13824){
            int u = idx / 96, r = idx % 96, f = r >> 1, o = r & 1;
            float acc = 0.f;
            #pragma unroll
            for (int k = 0; k < 16; k++) acc += Wo0[u*768 + k*48 + f] * Wt0[k*2 + o];
            g_Weff0[idx] = acc * s0;
        } else if (idx < 23040){
            int j = idx - 13824, u = j / 48, f = j % 48;
            float acc = 0.f;
            #pragma unroll
            for (int k = 0; k < 16; k++) acc += Wo1[u*768 + k*48 + f] * Wt1[k];
            g_Weff1[j] = acc * s12;
        } else if (idx < 32256){
            int j = idx - 23040, u = j / 48, f = j % 48;
            float acc = 0.f;
            #pragma unroll
            for (int k = 0; k < 16; k++) acc += Wo2[u*768 + k*48 + f] * Wt2[k];
            g_Weff2[j] = acc * s12;
        } else if (idx < 57600){
            int j = idx - 32256, p = j / 2304, r = j % 2304, v = r / 48, u = r % 48;
            g_tpwT[p*2304 + v*48 + u] = tpw[p*2304 + u*48 + v];
        }
    }
}

// ---------------- zero-fill that SKIPS occupied-slot diagonal positions ----------------
// Computes batch counts itself (no dependency on prep). Diagonal float4 of row r is
// col4 == r>>2; occupied slot = pos < count[b]. Node writes those; everything else zeroed.
__global__ void __launch_bounds__(256) k_zero_skip(float4* __restrict__ out, unsigned total4,
                                                   const int* __restrict__ batch, int n, int MN){
    __shared__ int cnt[BB];
    int tid = threadIdx.x;
    if (tid < BB) cnt[tid] = 0;
    __syncthreads();
    for (int i = tid; i < n; i += 256) atomicAdd(&cnt[batch[i]], 1);
    __syncthreads();

    const float4 z = make_float4(0.f, 0.f, 0.f, 0.f);
    unsigned stride = ZB * 256u;
    unsigned uMN = (unsigned)MN;
    for (unsigned i = blockIdx.x * 256u + tid; i < total4; i += stride){
        unsigned col4 = i % 48u;
        unsigned t = i / 48u;
        unsigned row = t % 192u;
        if (col4 == (row >> 2)){
            unsigned slot = (t / 192u) >> 1;          // strip P
            unsigned b = slot / uMN, pos = slot % uMN;
            if ((int)pos < cnt[b]) continue;          // node writes this diagonal float4
        }
        __stcs(out + i, z);
    }
}

// ---------------- fused per-node chain (round-12 proven: 43.3us with direct writes) ----------------
#define NT 1024
__global__ void __launch_bounds__(NT) k_node(const float* __restrict__ nf,
                                             const float* __restrict__ W0,
                                             const float* __restrict__ W1,
                                             const float* __restrict__ W2,
                                             float4* __restrict__ out, int n){
    int base = blockIdx.x * 2, tid = threadIdx.x;
    __shared__ float s_x[864];     // [nd][432]
    __shared__ float s_y[864];
    __shared__ float s_a[3360];    // [nd][1680]
    __shared__ float s_o[3360];
    __shared__ float s_g[960];     // [nd][480]

    const float sF = rsqrtf(48.f);
    int nn = (base + 2 <= n) ? 2 : (n - base);

    for (int i = tid; i < 864; i += NT)
        s_x[i] = (i < 432*nn) ? __ldg(nf + (size_t)base*432 + i) : 0.f;
    __syncthreads();

    // Phase 1: y[c*48+v] for both nodes; weight loaded once per (u,v)
    for (int i = tid; i < 432; i += NT){
        int c = i / 48, v = i % 48;
        const float* x0 = s_x;
        const float* x1 = s_x + 432;
        float a0=0.f,a1=0.f,a2=0.f,a3=0.f, b0=0.f,b1=0.f,b2=0.f,b3=0.f;
        if (c == 0){
            #pragma unroll
            for (int u = 0; u < 48; u += 4){
                float w0=__ldg(W0+u*48+v), w1=__ldg(W0+(u+1)*48+v), w2=__ldg(W0+(u+2)*48+v), w3=__ldg(W0+(u+3)*48+v);
                a0+=x0[u]*w0; a1+=x0[u+1]*w1; a2+=x0[u+2]*w2; a3+=x0[u+3]*w3;
                b0+=x1[u]*w0; b1+=x1[u+1]*w1; b2+=x1[u+2]*w2; b3+=x1[u+3]*w3;
            }
        } else if (c < 4){
            const int ii = c - 1;
            #pragma unroll
            for (int u = 0; u < 48; u += 4){
                float w0=__ldg(W1+u*48+v), w1=__ldg(W1+(u+1)*48+v), w2=__ldg(W1+(u+2)*48+v), w3=__ldg(W1+(u+3)*48+v);
                a0+=x0[48+u*3+ii]*w0; a1+=x0[48+(u+1)*3+ii]*w1; a2+=x0[48+(u+2)*3+ii]*w2; a3+=x0[48+(u+3)*3+ii]*w3;
                b0+=x1[48+u*3+ii]*w0; b1+=x1[48+(u+1)*3+ii]*w1; b2+=x1[48+(u+2)*3+ii]*w2; b3+=x1[48+(u+3)*3+ii]*w3;
            }
        } else {
            const int ii = c - 4;
            #pragma unroll
            for (int u = 0; u < 48; u += 4){
                float w0=__ldg(W2+u*48+v), w1=__ldg(W2+(u+1)*48+v), w2=__ldg(W2+(u+2)*48+v), w3=__ldg(W2+(u+3)*48+v);
                a0+=x0[192+u*5+ii]*w0; a1+=x0[192+(u+1)*5+ii]*w1; a2+=x0[192+(u+2)*5+ii]*w2; a3+=x0[192+(u+3)*5+ii]*w3;
                b0+=x1[192+u*5+ii]*w0; b1+=x1[192+(u+1)*5+ii]*w1; b2+=x1[192+(u+2)*5+ii]*w2; b3+=x1[192+(u+3)*5+ii]*w3;
            }
        }
        s_y[i]       = ((a0+a1)+(a2+a3)) * sF;
        s_y[432 + i] = ((b0+b1)+(b2+b3)) * sF;
    }
    __syncthreads();

    // Phase 2: a[j*48+u] for both nodes; coalesced weight loads reused 2x
    for (int i = tid; i < 1680; i += NT){
        int u = i % 48, j = i / 48;
        int p = c_j_p[j], c2 = c_j_c2[j];
        const float* y0 = s_y + c2*48;
        const float* y1 = s_y + 432 + c2*48;
        const float* wT = g_tpwT + p*2304 + u;
        float a0=0.f,a1=0.f,a2=0.f,a3=0.f, b0=0.f,b1=0.f,b2=0.f,b3=0.f;
        #pragma unroll
        for (int v = 0; v < 48; v += 4){
            float w0=__ldg(wT+v*48), w1=__ldg(wT+(v+1)*48), w2=__ldg(wT+(v+2)*48), w3=__ldg(wT+(v+3)*48);
            a0+=y0[v]*w0; a1+=y0[v+1]*w1; a2+=y0[v+2]*w2; a3+=y0[v+3]*w3;
            b0+=y1[v]*w0; b1+=y1[v+1]*w1; b2+=y1[v+2]*w2; b3+=y1[v+3]*w3;
        }
        s_a[i]        = ((a0+a1)+(a2+a3)) * sF;
        s_a[1680 + i] = ((b0+b1)+(b2+b3)) * sF;
    }
    __syncthreads();

    // Phase 3: CG contraction -> o (packed), both nodes (3360 items)
    for (int i = tid; i < 3360; i += NT){
        int nd = (i >= 1680);
        int ii = i - nd*1680;
        int u = ii % 48, os = ii / 48;
        int p = c_os_p[os], c3 = c_os_c3[os];
        int l1 = c_l1[p], l2 = c_l2[p];
        int n1 = 2*l1+1, n2 = 2*l2+1, n3 = 2*c_l3[p]+1;
        int cb1 = (l1 == 0) ? 0 : (l1 == 1) ? 1 : 4;
        int ao = c_aoff[p];
        const float* cg = g_CG + p*125 + c3;
        const float* yy = s_y + nd*432;
        const float* aa = s_a + nd*1680;
        float acc = 0.f;
        for (int m = 0; m < n1; m++){
            float ym = yy[(cb1 + m)*48 + u];
            for (int k = 0; k < n2; k++)
                acc += ym * aa[(ao + k)*48 + u] * __ldg(cg + (m*n2 + k)*n3);
        }
        s_o[nd*1680 + c_os_dst[os] + u] = acc;
    }
    __syncthreads();

    // Phase 4: g = o @ Weff, both nodes per thread (weights reused 2x)
    for (int i = tid; i < 480; i += NT){
        float a0=0.f,a1=0.f,a2=0.f,a3=0.f, b0=0.f,b1=0.f,b2=0.f,b3=0.f;
        if (i < 96){
            const float* o0 = s_o;
            const float* o1 = s_o + 1680;
            #pragma unroll
            for (int u = 0; u < 144; u += 4){
                float w0=__ldg(g_Weff0+u*96+i), w1=__ldg(g_Weff0+(u+1)*96+i), w2=__ldg(g_Weff0+(u+2)*96+i), w3=__ldg(g_Weff0+(u+3)*96+i);
                a0+=o0[u]*w0; a1+=o0[u+1]*w1; a2+=o0[u+2]*w2; a3+=o0[u+3]*w3;
                b0+=o1[u]*w0; b1+=o1[u+1]*w1; b2+=o1[u+2]*w2; b3+=o1[u+3]*w3;
            }
        } else if (i < 240){
            int j = i - 96, ii = j / 48, f = j % 48;
            const float* o0 = s_o + 144 + ii*192;
            const float* o1 = s_o + 1680 + 144 + ii*192;
            #pragma unroll
            for (int u = 0; u < 192; u += 4){
                float w0=__ldg(g_Weff1+u*48+f), w1=__ldg(g_Weff1+(u+1)*48+f), w2=__ldg(g_Weff1+(u+2)*48+f), w3=__ldg(g_Weff1+(u+3)*48+f);
                a0+=o0[u]*w0; a1+=o0[u+1]*w1; a2+=o0[u+2]*w2; a3+=o0[u+3]*w3;
                b0+=o1[u]*w0; b1+=o1[u+1]*w1; b2+=o1[u+2]*w2; b3+=o1[u+3]*w3;
            }
        } else {
            int j = i - 240, ii = j / 48, f = j % 48;
            const float* o0 = s_o + 720 + ii*192;
            const float* o1 = s_o + 1680 + 720 + ii*192;
            #pragma unroll
            for (int u = 0; u < 192; u += 4){
                float w0=__ldg(g_Weff2+u*48+f), w1=__ldg(g_Weff2+(u+1)*48+f), w2=__ldg(g_Weff2+(u+2)*48+f), w3=__ldg(g_Weff2+(u+3)*48+f);
                a0+=o0[u]*w0; a1+=o0[u+1]*w1; a2+=o0[u+2]*w2; a3+=o0[u+3]*w3;
                b0+=o1[u]*w0; b1+=o1[u+1]*w1; b2+=o1[u+2]*w2; b3+=o1[u+3]*w3;
            }
        }
        s_g[i]       = (a0+a1)+(a2+a3);
        s_g[480 + i] = (b0+b1)+(b2+b3);
    }
    __syncthreads();

    // Phase 5: assemble 4x4 M per (nd, f) and write diagonals DIRECTLY into d_out
    // (zero kernel skips exactly these positions -> no ordering needed)
    if (tid < 96){
        int nd = tid / 48, f = tid % 48;
        if (nd < nn){
            int slot = g_slotOf[base + nd];
            if (slot >= 0){
                const float* g = s_g + nd*480;
                float a0 = g[f*2 + 0], a1 = g[f*2 + 1];
                float v0 = g[96 + f], v1 = g[144 + f], v2 = g[192 + f];
                float dd[5];
                #pragma unroll
                for (int m = 0; m < 5; m++) dd[m] = g[240 + m*48 + f];
                const float* cg112 = g_CG + 5*125;   // path 5 = (1,1,2), (3,3,5)
                const float is3 = 0.57735026918962576f;
                float S[3][3];
                #pragma unroll
                for (int i = 0; i < 3; i++)
                #pragma unroll
                for (int j = 0; j < 3; j++){
                    float acc = (i == j) ? a1 * is3 : 0.f;
                    #pragma unroll
                    for (int m = 0; m < 5; m++) acc += dd[m] * cg112[i*15 + j*5 + m];
                    S[i][j] = acc;
                }
                float4 r0 = make_float4(a0, v0,      v1,      v2);
                float4 r1 = make_float4(v0, S[0][0], S[0][1], S[0][2]);
                float4 r2 = make_float4(v1, S[1][0], S[1][1], S[1][2]);
                float4 r3 = make_float4(v2, S[2][0], S[2][1], S[2][2]);
                #pragma unroll
                for (int pp = 0; pp < PP; pp++){
                    size_t b4 = (((size_t)slot*PP + pp)*DD + f*4)*48 + f;
                    out[b4]        = r0;
                    out[b4 + 48]   = r1;
                    out[b4 + 96]   = r2;
                    out[b4 + 144]  = r3;
                }
            }
        }
    }
}

// ---------------- launch ----------------
extern "C" void kernel_launch(void* const* d_in, const int* in_sizes, int n_in,
                              void* d_out, int out_size){
    const float* node_feats = (const float*)d_in[0];
    const float* W_lin0     = (const float*)d_in[1];
    const float* W_lin1     = (const float*)d_in[2];
    const float* W_lin2     = (const float*)d_in[3];
    const float* tp_w       = (const float*)d_in[4];
    const float* W_out0     = (const float*)d_in[5];
    const float* W_out1     = (const float*)d_in[6];
    const float* W_out2     = (const float*)d_in[7];
    const float* Wt0        = (const float*)d_in[8];
    const float* Wt1        = (const float*)d_in[9];
    const float* Wt2        = (const float*)d_in[10];
    const int*   batch      = (const int*)  d_in[11];

    int n  = in_sizes[0] / 432;
    int MN = out_size / (BB * PP * DD * DD);
    unsigned total4 = (unsigned)(out_size / 4);

    // Fully order-independent branches:
    //   A (s2): zero everything EXCEPT occupied-slot diagonals
    //   B (main): prep -> node (writes those diagonals directly)
    // Join only terminates the graph. No scatter kernel.
    cudaStream_t s2;
    cudaStreamCreateWithFlags(&s2, cudaStreamNonBlocking);
    cudaEvent_t evF, evJ;
    cudaEventCreateWithFlags(&evF, cudaEventDisableTiming);
    cudaEventCreateWithFlags(&evJ, cudaEventDisableTiming);

    cudaEventRecord(evF, 0);
    cudaStreamWaitEvent(s2, evF, 0);

    k_zero_skip<<<ZB, 256, 0, s2>>>((float4*)d_out, total4, batch, n, MN);
    cudaEventRecord(evJ, s2);

    k_prep<<<NPATH + 1 + 225, 256>>>(W_out0, W_out1, W_out2, Wt0, Wt1, Wt2, tp_w, batch, n, MN);
    k_node<<<(n + 1) / 2, NT>>>(node_feats, W_lin0, W_lin1, W_lin2, (float4*)d_out, n);

    cudaStreamWaitEvent(0, evJ, 0);

    cudaEventDestroy(evF);
    cudaEventDestroy(evJ);
    cudaStreamDestroy(s2);
}